// round 1
// baseline (speedup 1.0000x reference)
#include <cuda_runtime.h>

#define NN 8192
#define DIN 7
#define DH 8
#define DOUTK 23
#define NCHUNK 16
#define CJ (NN / NCHUNK)      /* 512 j per chunk  */
#define ITILE 128
#define NIT (NN / ITILE)      /* 64 i tiles       */

// -------- device scratch (no allocations allowed) --------
__device__ float4 g_wv[NN * 2];            // per j: {wv0..3},{wv4,wv5,wv6,w}
__device__ float g_cA[(NN / 2) * 4];       // per j-pair: {-x0a,-x0b,-x1a,-x1b}
__device__ float g_cB[(NN / 2) * 2];       // per j-pair: {-x2a,-x2b}
__device__ float g_part[NCHUNK][NN][8];    // chunk partial accumulators

__device__ __forceinline__ float leaky(float v) {
    return v >= 0.0f ? v : 0.01f * v;
}

// ---------------- Kernel A: per-node MLP + exp weights ----------------
__global__ void __launch_bounds__(128) prep_kernel(
    const float* __restrict__ x,
    const float* __restrict__ W1, const float* __restrict__ b1,
    const float* __restrict__ W2, const float* __restrict__ b2,
    const float* __restrict__ W3, const float* __restrict__ b3)
{
    __shared__ float sW1[DH * DIN], sb1[DH], sW2[DH * DH], sb2[DH],
                     sW3[DOUTK * DH], sb3[DOUTK];
    const int t = threadIdx.x;
    if (t < DH * DIN) sW1[t] = W1[t];
    if (t < DH) { sb1[t] = b1[t]; sb2[t] = b2[t]; }
    if (t < DH * DH) sW2[t] = W2[t];
    for (int k = t; k < DOUTK * DH; k += 128) sW3[k] = W3[k];
    if (t < DOUTK) sb3[t] = b3[t];
    __syncthreads();

    const int j = blockIdx.x * 128 + t;

    float xv[DIN];
#pragma unroll
    for (int k = 0; k < DIN; k++) xv[k] = x[j * DIN + k];

    float h1[DH];
#pragma unroll
    for (int c = 0; c < DH; c++) {
        float z = sb1[c];
#pragma unroll
        for (int k = 0; k < DIN; k++) z += sW1[c * DIN + k] * xv[k];
        h1[c] = leaky(z);
    }
    float h2[DH];
#pragma unroll
    for (int c = 0; c < DH; c++) {
        float z = sb2[c];
#pragma unroll
        for (int k = 0; k < DH; k++) z += sW2[c * DH + k] * h1[k];
        h2[c] = leaky(z);
    }
    float h3[DOUTK];
#pragma unroll
    for (int c = 0; c < DOUTK; c++) {
        float z = sb3[c];
#pragma unroll
        for (int k = 0; k < DH; k++) z += sW3[c * DH + k] * h2[k];
        h3[c] = z;   // layer 3 is linear
    }

    float s = 0.0f;
#pragma unroll
    for (int k = 0; k < 8; k++) s += h3[DIN + k] * h3[DIN + 8 + k];
    const float w = expf(s);

    g_wv[2 * j]     = make_float4(w * h3[0], w * h3[1], w * h3[2], w * h3[3]);
    g_wv[2 * j + 1] = make_float4(w * h3[4], w * h3[5], w * h3[6], w);

    const int jp = j >> 1, hh = j & 1;
    g_cA[jp * 4 + 0 + hh] = -xv[0];
    g_cA[jp * 4 + 2 + hh] = -xv[1];
    g_cB[jp * 2 + hh]     = -xv[2];
}

// ---------------- Kernel B: pairwise masked accumulation ----------------
__global__ void __launch_bounds__(128) pair_kernel(const float* __restrict__ x)
{
    __shared__ float4 s_wv[CJ * 2];       // 16 KB
    __shared__ float4 s_cA[CJ / 2];       //  4 KB
    __shared__ float2 s_cB[CJ / 2];       //  2 KB

    const int t = threadIdx.x;
    const int chunk = blockIdx.x;
    const int itile = blockIdx.y;

    {
        const float4* gwv = g_wv + chunk * CJ * 2;
        for (int k = t; k < CJ * 2; k += 128) s_wv[k] = gwv[k];
        const float4* gca = reinterpret_cast<const float4*>(g_cA) + chunk * (CJ / 2);
        for (int k = t; k < CJ / 2; k += 128) s_cA[k] = gca[k];
        const float2* gcb = reinterpret_cast<const float2*>(g_cB) + chunk * (CJ / 2);
        for (int k = t; k < CJ / 2; k += 128) s_cB[k] = gcb[k];
    }
    __syncthreads();

    const int i = itile * ITILE + t;
    const float c0 = __ldg(&x[i * DIN + 0]);
    const float c1 = __ldg(&x[i * DIN + 1]);
    const float c2 = __ldg(&x[i * DIN + 2]);
    unsigned long long ci00, ci11, ci22;
    asm("mov.b64 %0, {%1, %1};" : "=l"(ci00) : "f"(c0));
    asm("mov.b64 %0, {%1, %1};" : "=l"(ci11) : "f"(c1));
    asm("mov.b64 %0, {%1, %1};" : "=l"(ci22) : "f"(c2));

    unsigned long long acc0 = 0ull, acc1 = 0ull, acc2 = 0ull, acc3 = 0ull;

    const ulonglong2* wvp = reinterpret_cast<const ulonglong2*>(s_wv);
    const ulonglong2* cap = reinterpret_cast<const ulonglong2*>(s_cA);
    const unsigned long long* cbp =
        reinterpret_cast<const unsigned long long*>(s_cB);

#pragma unroll 2
    for (int jp = 0; jp < CJ / 2; jp++) {
        const ulonglong2 ca = cap[jp];
        const unsigned long long cb = cbp[jp];
        const ulonglong2 wA = wvp[4 * jp + 0];
        const ulonglong2 wB = wvp[4 * jp + 1];
        const ulonglong2 wC = wvp[4 * jp + 2];
        const ulonglong2 wD = wvp[4 * jp + 3];
        // Two pairs at once: lanes of each f32x2 hold (j_even, j_odd).
        // d = (|ci0-cj0| + |ci1-cj1|) + |ci2-cj2|  -- matches reference order.
        asm("{\n\t"
            ".reg .b64 u0, u1, u2, dd;\n\t"
            ".reg .b32 da, db;\n\t"
            ".reg .pred pa, pb;\n\t"
            "add.rn.f32x2 u0, %4, %7;\n\t"
            "add.rn.f32x2 u1, %5, %8;\n\t"
            "add.rn.f32x2 u2, %6, %9;\n\t"
            "and.b64 u0, u0, 0x7FFFFFFF7FFFFFFF;\n\t"
            "and.b64 u1, u1, 0x7FFFFFFF7FFFFFFF;\n\t"
            "and.b64 u2, u2, 0x7FFFFFFF7FFFFFFF;\n\t"
            "add.rn.f32x2 dd, u0, u1;\n\t"
            "add.rn.f32x2 dd, dd, u2;\n\t"
            "mov.b64 {da, db}, dd;\n\t"
            "setp.le.u32 pa, da, 0x40666666;\n\t"   // d <= 3.6f (bits, d>=0)
            "setp.le.u32 pb, db, 0x40666666;\n\t"
            "@pa add.rn.f32x2 %0, %0, %10;\n\t"
            "@pa add.rn.f32x2 %1, %1, %11;\n\t"
            "@pa add.rn.f32x2 %2, %2, %12;\n\t"
            "@pa add.rn.f32x2 %3, %3, %13;\n\t"
            "@pb add.rn.f32x2 %0, %0, %14;\n\t"
            "@pb add.rn.f32x2 %1, %1, %15;\n\t"
            "@pb add.rn.f32x2 %2, %2, %16;\n\t"
            "@pb add.rn.f32x2 %3, %3, %17;\n\t"
            "}"
            : "+l"(acc0), "+l"(acc1), "+l"(acc2), "+l"(acc3)
            : "l"(ci00), "l"(ci11), "l"(ci22),
              "l"(ca.x), "l"(ca.y), "l"(cb),
              "l"(wA.x), "l"(wA.y), "l"(wB.x), "l"(wB.y),
              "l"(wC.x), "l"(wC.y), "l"(wD.x), "l"(wD.y));
    }

    ulonglong2* po = reinterpret_cast<ulonglong2*>(&g_part[chunk][i][0]);
    po[0] = make_ulonglong2(acc0, acc1);
    po[1] = make_ulonglong2(acc2, acc3);
}

// ---------------- Kernel C: reduce partials + final MLP ----------------
__global__ void __launch_bounds__(128) final_kernel(
    const float* __restrict__ x,
    const float* __restrict__ We, const float* __restrict__ be,
    const float* __restrict__ Wd, const float* __restrict__ bd,
    float* __restrict__ out)
{
    __shared__ float sWe[DH * 2 * DIN], sbe[DH], sWd[DIN * DH], sbd[DIN];
    const int t = threadIdx.x;
    if (t < DH * 2 * DIN) sWe[t] = We[t];
    if (t < DH) sbe[t] = be[t];
    if (t < DIN * DH) sWd[t] = Wd[t];
    if (t < DIN) sbd[t] = bd[t];
    __syncthreads();

    const int i = blockIdx.x * 128 + t;

    float a[8];
#pragma unroll
    for (int k = 0; k < 8; k++) a[k] = 0.0f;
#pragma unroll
    for (int c = 0; c < NCHUNK; c++) {
        const float4* p = reinterpret_cast<const float4*>(&g_part[c][i][0]);
        const float4 pa = p[0], pb = p[1];
        a[0] += pa.x; a[1] += pa.y; a[2] += pa.z; a[3] += pa.w;
        a[4] += pb.x; a[5] += pb.y; a[6] += pb.z; a[7] += pb.w;
    }
    // subtract self contribution (self-pair always passes d=0 <= cutoff)
    const float4 wa = g_wv[2 * i], wb = g_wv[2 * i + 1];
    a[0] -= wa.x; a[1] -= wa.y; a[2] -= wa.z; a[3] -= wa.w;
    a[4] -= wb.x; a[5] -= wb.y; a[6] -= wb.z;
    const float denom = a[7] - wb.w;
    const float inv = 1.0f / fmaxf(denom, 1e-30f);

    float agg[DIN];
#pragma unroll
    for (int k = 0; k < DIN; k++) agg[k] = a[k] * inv;

    float xv[DIN];
#pragma unroll
    for (int k = 0; k < DIN; k++) xv[k] = x[i * DIN + k];

    float codes[DH];
#pragma unroll
    for (int c = 0; c < DH; c++) {
        float z = sbe[c];
#pragma unroll
        for (int k = 0; k < DIN; k++) z += sWe[c * (2 * DIN) + k] * xv[k];
#pragma unroll
        for (int k = 0; k < DIN; k++) z += sWe[c * (2 * DIN) + DIN + k] * agg[k];
        codes[c] = leaky(z);
    }
#pragma unroll
    for (int d = 0; d < DIN; d++) {
        float z = sbd[d];
#pragma unroll
        for (int c = 0; c < DH; c++) z += sWd[d * DH + c] * codes[c];
        out[i * DIN + d] = z;
    }
}

// ---------------- launch ----------------
extern "C" void kernel_launch(void* const* d_in, const int* in_sizes, int n_in,
                              void* d_out, int out_size)
{
    const float* x  = (const float*)d_in[0];
    const float* W1 = (const float*)d_in[1];
    const float* b1 = (const float*)d_in[2];
    const float* W2 = (const float*)d_in[3];
    const float* b2 = (const float*)d_in[4];
    const float* W3 = (const float*)d_in[5];
    const float* b3 = (const float*)d_in[6];
    const float* We = (const float*)d_in[7];
    const float* be = (const float*)d_in[8];
    const float* Wd = (const float*)d_in[9];
    const float* bd = (const float*)d_in[10];
    float* out = (float*)d_out;

    prep_kernel<<<NN / 128, 128>>>(x, W1, b1, W2, b2, W3, b3);
    dim3 grid(NCHUNK, NIT);
    pair_kernel<<<grid, 128>>>(x);
    final_kernel<<<NN / 128, 128>>>(x, We, be, Wd, bd, out);
}